// round 14
// baseline (speedup 1.0000x reference)
#include <cuda_runtime.h>
#include <cuda_bf16.h>
#include <cstdint>

#define NNODE 50000
#define NEDGE 800000
#define TOTE  (NNODE + NEDGE)
#define NEG_SLOPE 0.2f
#define BN_EPS 1e-5f
#define INV_SQRT2 0.7071067811865476f

// ---------------- scratch (device globals: no allocations allowed) -------------
// invariants across calls: g_cnt == 0 (re-zeroed by agg1 tail), as2/ad2/stats
// zeroed by fill_csr tail before use; first call relies on load-time zeros.
__device__ float g_h1  [NNODE * 128];
__device__ float g_out1[NNODE * 128];
__device__ float g_h2  [NNODE * 128];
__device__ float g_out2[NNODE * 128];
__device__ float g_res [NNODE * 128];
__device__ float g_as1[NNODE * 4];
__device__ float g_ad1[NNODE * 4];
__device__ float g_as2[NNODE];
__device__ float g_ad2[NNODE];
__device__ float g_stats[512];
__device__ int   g_cnt   [NNODE];
__device__ int   g_rowptr[NNODE + 1];
__device__ int   g_csrc  [TOTE];

__device__ __forceinline__ float dot4(float4 a, float4 b) {
    return a.x * b.x + a.y * b.y + a.z * b.z + a.w * b.w;
}
#define FMA4(a, s, v) { (a).x = fmaf((s), (v).x, (a).x); (a).y = fmaf((s), (v).y, (a).y); \
                        (a).z = fmaf((s), (v).z, (a).z); (a).w = fmaf((s), (v).w, (a).w); }

__device__ __forceinline__ uint32_t smem_to_u32(const void* smem_ptr) {
    uint32_t addr;
    asm("{ .reg .u64 tmp; cvta.to.shared.u64 tmp, %1; cvt.u32.u64 %0, tmp; }"
        : "=r"(addr) : "l"(smem_ptr));
    return addr;
}
__device__ __forceinline__ uint32_t f2bf2(float a, float b) {
    __nv_bfloat162 t = __floats2bfloat162_rn(a, b);
    return *reinterpret_cast<uint32_t*>(&t);
}

// baseline-PTX tensor ops (HMMA/LDSM SASS on sm_103)
#define LDSM4(R, addr) \
    asm volatile("ldmatrix.sync.aligned.m8n8.x4.shared.b16 {%0,%1,%2,%3}, [%4];" \
        : "=r"((R)[0]), "=r"((R)[1]), "=r"((R)[2]), "=r"((R)[3]) : "r"(addr))
#define LDSM2(R, addr) \
    asm volatile("ldmatrix.sync.aligned.m8n8.x2.shared.b16 {%0,%1}, [%2];" \
        : "=r"((R)[0]), "=r"((R)[1]) : "r"(addr))
#define MMA_BF16(D, Ar, Br) \
    asm volatile("mma.sync.aligned.m16n8k16.row.col.f32.bf16.bf16.f32 " \
        "{%0,%1,%2,%3}, {%4,%5,%6,%7}, {%8,%9}, {%0,%1,%2,%3};" \
        : "+f"((D)[0]), "+f"((D)[1]), "+f"((D)[2]), "+f"((D)[3]) \
        : "r"((Ar)[0]), "r"((Ar)[1]), "r"((Ar)[2]), "r"((Ar)[3]), \
          "r"((Br)[0]), "r"((Br)[1]))

// ---------------- CSR build -------------------------------------------------------
__global__ void hist(const int* __restrict__ ei, int E, int stride) {
    int t = blockIdx.x * blockDim.x + threadIdx.x;
#pragma unroll
    for (int k = 0; k < 4; k++) {
        int e = t + k * stride;
        if (e < E) atomicAdd(&g_cnt[ei[E + e]], 1);
    }
}
__global__ void scan_rowptr(int N) {
    __shared__ int s_sum[1024];
    int t = threadIdx.x;
    int chunk = (N + 1023) >> 10;
    int b0 = t * chunk, b1 = min(b0 + chunk, N);
    int s = 0;
    for (int i = b0; i < b1; i++) s += g_cnt[i] + 1;   // +1 self-loop
    s_sum[t] = s;
    __syncthreads();
    for (int off = 1; off < 1024; off <<= 1) {
        int v = (t >= off) ? s_sum[t - off] : 0;
        __syncthreads();
        s_sum[t] += v;
        __syncthreads();
    }
    int run = (t == 0) ? 0 : s_sum[t - 1];
    for (int i = b0; i < b1; i++) {
        int c = g_cnt[i] + 1;
        g_rowptr[i] = run;
        g_cnt[i] = run;          // cursor for fill
        run += c;
    }
    if (t == 1023) g_rowptr[N] = s_sum[1023];
}
// fill + tail blocks zero as2/ad2/stats (eCsr orders these before their consumers)
__global__ void fill_csr(const int* __restrict__ ei, int E, int N,
                         int stride, int fillBlks) {
    if ((int)blockIdx.x >= fillBlks) {
        int t = (blockIdx.x - fillBlks) * 256 + threadIdx.x;
        int zstride = (gridDim.x - fillBlks) * 256;
        for (int i = t; i < N; i += zstride) { g_as2[i] = 0.f; g_ad2[i] = 0.f; }
        if (t < 512) g_stats[t] = 0.f;
        return;
    }
    int t = blockIdx.x * blockDim.x + threadIdx.x;
    int tot = E + N;
#pragma unroll
    for (int k = 0; k < 4; k++) {
        int e = t + k * stride;
        if (e < tot) {
            int s, d;
            if (e < E) { s = ei[e]; d = ei[E + e]; }
            else       { s = d = e - E; }
            int pos = atomicAdd(&g_cnt[d], 1);
            g_csrc[pos] = s;
        }
    }
}

// ---------------- warp-mma bf16-split GEMM (column-split, 2 CTAs/SM) -------------
// Block computes C[128, 64] half-tile (blockIdx.y = ch). D = XhiWhi+XhiWlo+XloWhi.
// 256 threads; warp w: rows (w&3)*32, local cols (w>>2)*32 (2 m-tiles x 4 n-tiles,
// 32 accumulators). SMEM: Xhi | Xlo | WThi(64 rows) | WTlo = 102KB.
// MODE 0: C += bias (p0). MODE 1: warp's 32 cols = ONE head -> direct logit store.
// MODE 2: X := relu(BN1(A)); 1-head logits -> atomicAdd g_as2/g_ad2.
#define TGS 136                 // padded bf16 row stride
#define OFF_XHI 0
#define OFF_XLO 34816
#define OFF_WHI 69632
#define OFF_WLO 87040
#define TG_SMEM 104448

template<int MODE>
__global__ void __launch_bounds__(256, 2)
tgemm(const float* __restrict__ A, const float* __restrict__ W,
      const float* __restrict__ p0, const float* __restrict__ p1,
      const float* __restrict__ gamma, const float* __restrict__ beta,
      float* __restrict__ C, int nrows) {
    extern __shared__ char smem[];
    __shared__ float sb0[128], sb1[128];
    __shared__ float s_sc[128], s_off[128];
    uint32_t sb = smem_to_u32(smem);
    const int tid = threadIdx.x;
    const int lane = tid & 31, w = tid >> 5;
    const int ch = blockIdx.y;           // column half: cols [ch*64, ch*64+64)
    const int rb0 = blockIdx.x * 128;

    if (tid < 128) {
        sb0[tid] = p0[tid];
        if (MODE >= 1) sb1[tid] = p1[tid];
        if (MODE == 2) {
            float invN = 1.f / (float)nrows;
            float mu = g_stats[tid] * invN;
            float var = g_stats[128 + tid] * invN - mu * mu;
            float sc = gamma[tid] * rsqrtf(var + BN_EPS);
            s_sc[tid] = sc;
            s_off[tid] = beta[tid] - mu * sc;
        }
    }
    __syncthreads();   // s_sc needed by X staging in MODE 2

    // ---- W[k][ch*64 + n] -> WT[n][k] hi/lo bf16 (coalesced reads) ----
    for (int idx = tid; idx < 8192; idx += 256) {
        int k = idx >> 6, n = idx & 63;
        float wv = W[k * 128 + ch * 64 + n];
        __nv_bfloat16 hb = __float2bfloat16_rn(wv);
        float hf = __bfloat162float(hb);
        __nv_bfloat16 lb = __float2bfloat16_rn(wv - hf);
        int off = (n * TGS + k) * 2;
        *(__nv_bfloat16*)(smem + OFF_WHI + off) = hb;
        *(__nv_bfloat16*)(smem + OFF_WLO + off) = lb;
    }

    // ---- X rows -> Xhi/Xlo bf16 (BN1+relu fused in MODE 2) ----
    {
        const float4* A4 = (const float4*)A;
        for (int i = tid; i < 4096; i += 256) {
            int r = i >> 5, kk = i & 31;   // kk = float4 index (4 channels)
            int row = rb0 + r;
            float4 v = make_float4(0.f, 0.f, 0.f, 0.f);
            if (row < nrows) {
                v = A4[(long)row * 32 + kk];
                if (MODE == 2) {
                    int c0 = kk * 4;
                    v.x = fmaxf(fmaf(v.x, s_sc[c0 + 0], s_off[c0 + 0]), 0.f);
                    v.y = fmaxf(fmaf(v.y, s_sc[c0 + 1], s_off[c0 + 1]), 0.f);
                    v.z = fmaxf(fmaf(v.z, s_sc[c0 + 2], s_off[c0 + 2]), 0.f);
                    v.w = fmaxf(fmaf(v.w, s_sc[c0 + 3], s_off[c0 + 3]), 0.f);
                }
            }
            float hx = __bfloat162float(__float2bfloat16_rn(v.x));
            float hy = __bfloat162float(__float2bfloat16_rn(v.y));
            float hz = __bfloat162float(__float2bfloat16_rn(v.z));
            float hw = __bfloat162float(__float2bfloat16_rn(v.w));
            uint2 hh = make_uint2(f2bf2(hx, hy), f2bf2(hz, hw));
            uint2 ll = make_uint2(f2bf2(v.x - hx, v.y - hy), f2bf2(v.z - hz, v.w - hw));
            int off = (r * TGS + kk * 4) * 2;
            *(uint2*)(smem + OFF_XHI + off) = hh;
            *(uint2*)(smem + OFF_XLO + off) = ll;
        }
    }
    __syncthreads();

    // ---- mainloop: 3 split terms, K in 8 steps of 16 ----
    const int rowg = (w & 3) * 32;       // warp rows within tile
    const int colg = (w >> 2) * 32;      // warp cols within the 64-col half
    float d[2][4][4];
#pragma unroll
    for (int mt = 0; mt < 2; mt++)
#pragma unroll
        for (int nt = 0; nt < 4; nt++)
#pragma unroll
            for (int q = 0; q < 4; q++) d[mt][nt][q] = 0.f;

    const int aRow = (lane & 7) + ((lane >> 3) & 1) * 8;  // row within m16 tile
    const int aKof = (lane >> 4) * 8;                     // k offset within k16
    const int bRow = lane & 7;                            // n within n8 tile
    const int bKof = ((lane >> 3) & 1) * 8;

    const uint32_t xbs[3] = { sb + OFF_XHI, sb + OFF_XHI, sb + OFF_XLO };
    const uint32_t wbs[3] = { sb + OFF_WHI, sb + OFF_WLO, sb + OFF_WHI };
    for (int t = 0; t < 3; t++) {
        uint32_t Xb = xbs[t], Wb = wbs[t];
#pragma unroll
        for (int kt = 0; kt < 8; kt++) {
            uint32_t a0[4], a1[4];
            uint32_t aAddr = Xb + (uint32_t)(((rowg + aRow) * TGS + kt * 16 + aKof) * 2);
            LDSM4(a0, aAddr);
            LDSM4(a1, aAddr + 16 * TGS * 2);
            uint32_t b[4][2];
#pragma unroll
            for (int nt = 0; nt < 4; nt++) {
                uint32_t bAddr = Wb + (uint32_t)(((colg + nt * 8 + bRow) * TGS + kt * 16 + bKof) * 2);
                LDSM2(b[nt], bAddr);
            }
#pragma unroll
            for (int nt = 0; nt < 4; nt++) {
                MMA_BF16(d[0][nt], a0, b[nt]);
                MMA_BF16(d[1][nt], a1, b[nt]);
            }
        }
    }

    // ---- epilogue ----
    const int qr = lane >> 2;
    const int qc = (lane & 3) * 2;
    const int gc0 = ch * 64 + colg;      // global col base for this warp
    const int head = gc0 >> 5;           // MODE 1: this warp covers exactly 1 head

#pragma unroll
    for (int mt = 0; mt < 2; mt++) {
        int r0 = rb0 + rowg + mt * 16 + qr;
        int r1 = r0 + 8;
        if (MODE == 0) {
#pragma unroll
            for (int nt = 0; nt < 4; nt++) {
                int c = gc0 + nt * 8 + qc;
                float b0 = sb0[c], b1 = sb0[c + 1];
                if (r0 < nrows)
                    *(float2*)&C[(long)r0 * 128 + c] =
                        make_float2(d[mt][nt][0] + b0, d[mt][nt][1] + b1);
                if (r1 < nrows)
                    *(float2*)&C[(long)r1 * 128 + c] =
                        make_float2(d[mt][nt][2] + b0, d[mt][nt][3] + b1);
            }
        } else {
            float ps0 = 0.f, pd0 = 0.f, ps1 = 0.f, pd1 = 0.f;
#pragma unroll
            for (int nt = 0; nt < 4; nt++) {
                int c = gc0 + nt * 8 + qc;
                float a0 = sb0[c], a1 = sb0[c + 1];
                float e0 = sb1[c], e1 = sb1[c + 1];
                ps0 += d[mt][nt][0] * a0 + d[mt][nt][1] * a1;
                pd0 += d[mt][nt][0] * e0 + d[mt][nt][1] * e1;
                ps1 += d[mt][nt][2] * a0 + d[mt][nt][3] * a1;
                pd1 += d[mt][nt][2] * e0 + d[mt][nt][3] * e1;
                if (r0 < nrows)
                    *(float2*)&C[(long)r0 * 128 + c] = make_float2(d[mt][nt][0], d[mt][nt][1]);
                if (r1 < nrows)
                    *(float2*)&C[(long)r1 * 128 + c] = make_float2(d[mt][nt][2], d[mt][nt][3]);
            }
            // reduce over the 4 lanes sharing a row (segments of width 4)
#define QRED(v) { v += __shfl_down_sync(0xffffffffu, v, 2, 4); \
                  v += __shfl_down_sync(0xffffffffu, v, 1, 4); }
            QRED(ps0) QRED(pd0) QRED(ps1) QRED(pd1)
#undef QRED
            if ((lane & 3) == 0) {
                if (MODE == 1) {
                    if (r0 < nrows) { g_as1[r0 * 4 + head] = ps0; g_ad1[r0 * 4 + head] = pd0; }
                    if (r1 < nrows) { g_as1[r1 * 4 + head] = ps1; g_ad1[r1 * 4 + head] = pd1; }
                } else {
                    if (r0 < nrows) {
                        atomicAdd(&g_as2[r0], ps0);
                        atomicAdd(&g_ad2[r0], pd0);
                    }
                    if (r1 < nrows) {
                        atomicAdd(&g_as2[r1], ps1);
                        atomicAdd(&g_ad2[r1], pd1);
                    }
                }
            }
        }
    }
}

// ---- final GEMM [N,128]x[128,32], fused BN2+relu+residual+1/sqrt2 --------------
__global__ void gemm32f(const float* __restrict__ A, const float* __restrict__ W,
                        const float* __restrict__ bias_fin,
                        const float* __restrict__ gamma2,
                        const float* __restrict__ beta2,
                        const float* __restrict__ Rres,
                        float* __restrict__ C, int nrows) {
    __shared__ float Ws[128 * 32];
    __shared__ float Xs[32 * 128];
    __shared__ float s_sc[128], s_off[128];
    int tid = threadIdx.x;
    {
        float invN = 1.f / (float)nrows;
        float mu = g_stats[256 + tid] * invN;
        float var = g_stats[384 + tid] * invN - mu * mu;
        float sc = gamma2[tid] * rsqrtf(var + BN_EPS);
        s_sc[tid] = sc;
        s_off[tid] = beta2[tid] - mu * sc;
    }
    for (int i = tid; i < 4096; i += 128) Ws[i] = W[i];
    int w = tid >> 5, l = tid & 31;
    float bv = bias_fin[l];
    int rb0 = blockIdx.x * 128;
    const float4* A4 = (const float4*)A;
    const float4* R4 = (const float4*)Rres;

    for (int t = 0; t < 4; t++) {
        int rbase = rb0 + t * 32;
        __syncthreads();
        float4* Xs4 = (float4*)Xs;
        for (int i = tid; i < 1024; i += 128) {
            int r = i >> 5, cc = i & 31;
            int rrow = rbase + r;
            float4 xv = make_float4(0.f, 0.f, 0.f, 0.f);
            if (rrow < nrows) {
                float4 raw = A4[(long)rrow * 32 + cc];
                float4 rs  = R4[(long)rrow * 32 + cc];
                int c0 = cc * 4;
                float v;
                v = fmaxf(fmaf(raw.x, s_sc[c0 + 0], s_off[c0 + 0]), 0.f);
                xv.x = (v + rs.x) * INV_SQRT2;
                v = fmaxf(fmaf(raw.y, s_sc[c0 + 1], s_off[c0 + 1]), 0.f);
                xv.y = (v + rs.y) * INV_SQRT2;
                v = fmaxf(fmaf(raw.z, s_sc[c0 + 2], s_off[c0 + 2]), 0.f);
                xv.z = (v + rs.z) * INV_SQRT2;
                v = fmaxf(fmaf(raw.w, s_sc[c0 + 3], s_off[c0 + 3]), 0.f);
                xv.w = (v + rs.w) * INV_SQRT2;
            }
            Xs4[i] = xv;
        }
        __syncthreads();
        float acc[8] = {};
#pragma unroll 4
        for (int k = 0; k < 128; k++) {
            float wv = Ws[k * 32 + l];
#pragma unroll
            for (int r = 0; r < 8; r++)
                acc[r] = fmaf(Xs[(w * 8 + r) * 128 + k], wv, acc[r]);
        }
#pragma unroll
        for (int r = 0; r < 8; r++) {
            int rrow = rbase + w * 8 + r;
            if (rrow < nrows) C[(long)rrow * 32 + l] = acc[r] + bv;
        }
    }
}

// ---------------- aggregation + fused BN stats ------------------------------------
// agg1 tail blocks re-zero g_cnt for the next call (after fill_csr's last use).
__global__ void agg1(const float* __restrict__ bias, int N, int aggBlks) {
    if ((int)blockIdx.x >= aggBlks) {
        int t = (blockIdx.x - aggBlks) * 256 + threadIdx.x;
        int stride = (gridDim.x - aggBlks) * 256;
        for (int i = t; i < N; i += stride) g_cnt[i] = 0;
        return;
    }
    __shared__ int   s_src[8][32];
    __shared__ float s_ee [8][128];
    __shared__ float s_stat[256];
    int tid = threadIdx.x;
    s_stat[tid] = 0.f;
    __syncthreads();
    int wl = tid >> 5;
    int gw = (blockIdx.x * blockDim.x + tid) >> 5;
    int l = tid & 31;
    if (gw < N) {
        int beg = __ldg(&g_rowptr[gw]), end = __ldg(&g_rowptr[gw + 1]);
        float4 adv = *(const float4*)(g_ad1 + gw * 4);
        int head = l >> 3;
        float4 acc = make_float4(0.f, 0.f, 0.f, 0.f);
        float4 den = make_float4(0.f, 0.f, 0.f, 0.f);
        for (int base = beg; base < end; base += 32) {
            int e = base + l;
            if (e < end) {
                int s = __ldg(&g_csrc[e]);
                float4 as = *(const float4*)(g_as1 + s * 4);
                float vx = as.x + adv.x; vx = vx > 0.f ? vx : NEG_SLOPE * vx;
                float vy = as.y + adv.y; vy = vy > 0.f ? vy : NEG_SLOPE * vy;
                float vz = as.z + adv.z; vz = vz > 0.f ? vz : NEG_SLOPE * vz;
                float vw = as.w + adv.w; vw = vw > 0.f ? vw : NEG_SLOPE * vw;
                float4 ee;
                ee.x = __expf(vx); ee.y = __expf(vy);
                ee.z = __expf(vz); ee.w = __expf(vw);
                den.x += ee.x; den.y += ee.y; den.z += ee.z; den.w += ee.w;
                s_src[wl][l] = s;
                ((float4*)s_ee[wl])[l] = ee;
            }
            __syncwarp();
            int cnt = min(32, end - base);
            int j = 0;
            for (; j + 4 <= cnt; j += 4) {
                int s0 = s_src[wl][j],     s1 = s_src[wl][j + 1];
                int s2 = s_src[wl][j + 2], s3 = s_src[wl][j + 3];
                float e0 = s_ee[wl][(j    ) * 4 + head];
                float e1 = s_ee[wl][(j + 1) * 4 + head];
                float e2 = s_ee[wl][(j + 2) * 4 + head];
                float e3 = s_ee[wl][(j + 3) * 4 + head];
                float4 h0 = *(const float4*)(g_h1 + (long)s0 * 128 + l * 4);
                float4 h1 = *(const float4*)(g_h1 + (long)s1 * 128 + l * 4);
                float4 h2 = *(const float4*)(g_h1 + (long)s2 * 128 + l * 4);
                float4 h3 = *(const float4*)(g_h1 + (long)s3 * 128 + l * 4);
                FMA4(acc, e0, h0);
                FMA4(acc, e1, h1);
                FMA4(acc, e2, h2);
                FMA4(acc, e3, h3);
            }
            for (; j < cnt; j++) {
                int ss   = s_src[wl][j];
                float eh = s_ee[wl][j * 4 + head];
                float4 hv = *(const float4*)(g_h1 + (long)ss * 128 + l * 4);
                FMA4(acc, eh, hv);
            }
            __syncwarp();
        }
#pragma unroll
        for (int off = 16; off; off >>= 1) {
            den.x += __shfl_xor_sync(0xffffffffu, den.x, off);
            den.y += __shfl_xor_sync(0xffffffffu, den.y, off);
            den.z += __shfl_xor_sync(0xffffffffu, den.z, off);
            den.w += __shfl_xor_sync(0xffffffffu, den.w, off);
        }
        float dh = head == 0 ? den.x : head == 1 ? den.y : head == 2 ? den.z : den.w;
        float inv = __fdividef(1.f, dh + 1e-16f);
        float4 bv = ((const float4*)bias)[l];
        float4 o = make_float4(acc.x * inv + bv.x, acc.y * inv + bv.y,
                               acc.z * inv + bv.z, acc.w * inv + bv.w);
        ((float4*)g_out1)[(long)gw * 32 + l] = o;
        int c0 = l * 4;
        atomicAdd(&s_stat[c0 + 0], o.x);
        atomicAdd(&s_stat[c0 + 1], o.y);
        atomicAdd(&s_stat[c0 + 2], o.z);
        atomicAdd(&s_stat[c0 + 3], o.w);
        atomicAdd(&s_stat[128 + c0 + 0], o.x * o.x);
        atomicAdd(&s_stat[128 + c0 + 1], o.y * o.y);
        atomicAdd(&s_stat[128 + c0 + 2], o.z * o.z);
        atomicAdd(&s_stat[128 + c0 + 3], o.w * o.w);
    }
    __syncthreads();
    atomicAdd(&g_stats[tid], s_stat[tid]);
}

__global__ void agg2(const float* __restrict__ bias, int N) {
    __shared__ int   s_src[8][32];
    __shared__ float s_ee [8][32];
    __shared__ float s_stat[256];
    int tid = threadIdx.x;
    s_stat[tid] = 0.f;
    __syncthreads();
    int wl = tid >> 5;
    int gw = (blockIdx.x * blockDim.x + tid) >> 5;
    int l = tid & 31;
    if (gw < N) {
        int beg = __ldg(&g_rowptr[gw]), end = __ldg(&g_rowptr[gw + 1]);
        float adv = g_ad2[gw];
        float4 acc = make_float4(0.f, 0.f, 0.f, 0.f);
        float den = 0.f;
        for (int base = beg; base < end; base += 32) {
            int e = base + l;
            if (e < end) {
                int s = __ldg(&g_csrc[e]);
                float v = __ldg(g_as2 + s) + adv;
                v = v > 0.f ? v : NEG_SLOPE * v;
                float ee = __expf(v);
                den += ee;
                s_src[wl][l] = s;
                s_ee[wl][l] = ee;
            }
            __syncwarp();
            int cnt = min(32, end - base);
            int j = 0;
            for (; j + 4 <= cnt; j += 4) {
                int s0 = s_src[wl][j],     s1 = s_src[wl][j + 1];
                int s2 = s_src[wl][j + 2], s3 = s_src[wl][j + 3];
                float e0 = s_ee[wl][j],     e1 = s_ee[wl][j + 1];
                float e2 = s_ee[wl][j + 2], e3 = s_ee[wl][j + 3];
                float4 h0 = *(const float4*)(g_h2 + (long)s0 * 128 + l * 4);
                float4 h1 = *(const float4*)(g_h2 + (long)s1 * 128 + l * 4);
                float4 h2 = *(const float4*)(g_h2 + (long)s2 * 128 + l * 4);
                float4 h3 = *(const float4*)(g_h2 + (long)s3 * 128 + l * 4);
                FMA4(acc, e0, h0);
                FMA4(acc, e1, h1);
                FMA4(acc, e2, h2);
                FMA4(acc, e3, h3);
            }
            for (; j < cnt; j++) {
                int ss   = s_src[wl][j];
                float ej = s_ee[wl][j];
                float4 hv = *(const float4*)(g_h2 + (long)ss * 128 + l * 4);
                FMA4(acc, ej, hv);
            }
            __syncwarp();
        }
#pragma unroll
        for (int off = 16; off; off >>= 1)
            den += __shfl_xor_sync(0xffffffffu, den, off);
        float inv = __fdividef(1.f, den + 1e-16f);
        float4 bv = ((const float4*)bias)[l];
        float4 o = make_float4(acc.x * inv + bv.x, acc.y * inv + bv.y,
                               acc.z * inv + bv.z, acc.w * inv + bv.w);
        ((float4*)g_out2)[(long)gw * 32 + l] = o;
        int c0 = l * 4;
        atomicAdd(&s_stat[c0 + 0], o.x);
        atomicAdd(&s_stat[c0 + 1], o.y);
        atomicAdd(&s_stat[c0 + 2], o.z);
        atomicAdd(&s_stat[c0 + 3], o.w);
        atomicAdd(&s_stat[128 + c0 + 0], o.x * o.x);
        atomicAdd(&s_stat[128 + c0 + 1], o.y * o.y);
        atomicAdd(&s_stat[128 + c0 + 2], o.z * o.z);
        atomicAdd(&s_stat[128 + c0 + 3], o.w * o.w);
    }
    __syncthreads();
    atomicAdd(&g_stats[256 + tid], s_stat[tid]);
}

// ---------------- launch ------------------------------------------------------
extern "C" void kernel_launch(void* const* d_in, const int* in_sizes, int n_in,
                              void* d_out, int out_size) {
    const float* x        = (const float*)d_in[0];
    const int*   ei       = (const int*)  d_in[1];
    const float* W1       = (const float*)d_in[2];
    const float* att_src1 = (const float*)d_in[3];
    const float* att_dst1 = (const float*)d_in[4];
    const float* bias1    = (const float*)d_in[5];
    const float* W2       = (const float*)d_in[6];
    const float* att_src2 = (const float*)d_in[7];
    const float* att_dst2 = (const float*)d_in[8];
    const float* bias2    = (const float*)d_in[9];
    const float* gamma1   = (const float*)d_in[10];
    const float* beta1    = (const float*)d_in[11];
    const float* gamma2   = (const float*)d_in[12];
    const float* beta2    = (const float*)d_in[13];
    const float* W_res    = (const float*)d_in[14];
    const float* b_res    = (const float*)d_in[15];
    const float* W_fin    = (const float*)d_in[16];
    const float* b_fin    = (const float*)d_in[17];
    float* out = (float*)d_out;

    int N = in_sizes[0] / 128;
    int E = in_sizes[1] / 2;
    int tot = E + N;

    float *p_h1, *p_out1, *p_h2, *p_out2, *p_res;
    cudaGetSymbolAddress((void**)&p_h1,   g_h1);
    cudaGetSymbolAddress((void**)&p_out1, g_out1);
    cudaGetSymbolAddress((void**)&p_h2,   g_h2);
    cudaGetSymbolAddress((void**)&p_out2, g_out2);
    cudaGetSymbolAddress((void**)&p_res,  g_res);

    cudaFuncSetAttribute(tgemm<0>, cudaFuncAttributeMaxDynamicSharedMemorySize, TG_SMEM);
    cudaFuncSetAttribute(tgemm<1>, cudaFuncAttributeMaxDynamicSharedMemorySize, TG_SMEM);
    cudaFuncSetAttribute(tgemm<2>, cudaFuncAttributeMaxDynamicSharedMemorySize, TG_SMEM);

    static cudaStream_t sA = 0, sB = 0;
    static cudaEvent_t  eFork = 0, eA4 = 0, eCsr = 0, eRes = 0;
    static int s_init = 0;
    if (!s_init) {
        s_init = 1;
        cudaStreamCreateWithFlags(&sA, cudaStreamNonBlocking);
        cudaStreamCreateWithFlags(&sB, cudaStreamNonBlocking);
        cudaEventCreateWithFlags(&eFork, cudaEventDisableTiming);
        cudaEventCreateWithFlags(&eA4,   cudaEventDisableTiming);
        cudaEventCreateWithFlags(&eCsr,  cudaEventDisableTiming);
        cudaEventCreateWithFlags(&eRes,  cudaEventDisableTiming);
    }

    int nrb = (N + 127) / 128;
    dim3 gg(nrb, 2);                       // column-split GEMM grid
    int aw = (N * 32 + 255) / 256;
    int cleanBlks = 64;

    cudaStream_t m = 0;

    // fork: CSR build chain on sA (g_cnt is zero from previous call / load-time)
    cudaEventRecord(eFork, m);
    cudaStreamWaitEvent(sA, eFork, 0);
    int hthreads = (E + 3) / 4;
    int hblocks = (hthreads + 255) / 256;
    hist<<<hblocks, 256, 0, sA>>>(ei, E, hblocks * 256);
    scan_rowptr<<<1, 1024, 0, sA>>>(N);
    int fthreads = (tot + 3) / 4;
    int fblocks = (fthreads + 255) / 256;
    fill_csr<<<fblocks + 64, 256, 0, sA>>>(ei, E, N, fblocks * 256, fblocks);
    cudaEventRecord(eCsr, sA);

    // main: conv1 tensor GEMM (+4-head logits)
    tgemm<1><<<gg, 256, TG_SMEM, m>>>(x, W1, att_src1, att_dst1,
                                      nullptr, nullptr, p_h1, N);

    // fork: residual tensor GEMM on sB (overlaps agg1)
    cudaEventRecord(eA4, m);
    cudaStreamWaitEvent(sB, eA4, 0);
    tgemm<0><<<gg, 256, TG_SMEM, sB>>>(x, W_res, b_res, b_res,
                                       nullptr, nullptr, p_res, N);
    cudaEventRecord(eRes, sB);

    // main: join CSR, conv1 aggregation (+BN1 stats; tail re-zeroes g_cnt)
    cudaStreamWaitEvent(m, eCsr, 0);
    agg1<<<aw + cleanBlks, 256, 0, m>>>(bias1, N, aw);

    // conv2 tensor GEMM (BN1+relu fused, 1-head logits via atomics)
    tgemm<2><<<gg, 256, TG_SMEM, m>>>(p_out1, W2, att_src2, att_dst2,
                                      gamma1, beta1, p_h2, N);
    agg2<<<aw, 256, 0, m>>>(bias2, N);

    // join residual, final projection
    cudaStreamWaitEvent(m, eRes, 0);
    gemm32f<<<(N + 127) / 128, 128, 0, m>>>(p_out2, W_fin, b_fin,
                                            gamma2, beta2, p_res, out, N);
}

// round 15
// speedup vs baseline: 1.3618x; 1.3618x over previous
#include <cuda_runtime.h>
#include <cuda_bf16.h>
#include <cstdint>

#define NNODE 50000
#define NEDGE 800000
#define TOTE  (NNODE + NEDGE)
#define NEG_SLOPE 0.2f
#define BN_EPS 1e-5f
#define INV_SQRT2 0.7071067811865476f

// ---------------- scratch (device globals: no allocations allowed) -------------
// invariants across calls: g_cnt == 0 (re-zeroed by agg1 tail), as2/ad2/stats
// zeroed by fill_csr tail before use; first call relies on load-time zeros.
__device__ float g_h1  [NNODE * 128];
__device__ float g_out1[NNODE * 128];
__device__ float g_h2  [NNODE * 128];
__device__ float g_out2[NNODE * 128];
__device__ float g_res [NNODE * 128];
__device__ float g_as1[NNODE * 4];
__device__ float g_ad1[NNODE * 4];
__device__ float g_as2[NNODE];
__device__ float g_ad2[NNODE];
__device__ float g_stats[512];
__device__ int   g_cnt   [NNODE];
__device__ int   g_rowptr[NNODE + 1];
__device__ int   g_csrc  [TOTE];

__device__ __forceinline__ float dot4(float4 a, float4 b) {
    return a.x * b.x + a.y * b.y + a.z * b.z + a.w * b.w;
}
#define FMA4(a, s, v) { (a).x = fmaf((s), (v).x, (a).x); (a).y = fmaf((s), (v).y, (a).y); \
                        (a).z = fmaf((s), (v).z, (a).z); (a).w = fmaf((s), (v).w, (a).w); }

__device__ __forceinline__ uint32_t smem_to_u32(const void* smem_ptr) {
    uint32_t addr;
    asm("{ .reg .u64 tmp; cvta.to.shared.u64 tmp, %1; cvt.u32.u64 %0, tmp; }"
        : "=r"(addr) : "l"(smem_ptr));
    return addr;
}
__device__ __forceinline__ uint32_t f2bf2(float a, float b) {
    __nv_bfloat162 t = __floats2bfloat162_rn(a, b);
    return *reinterpret_cast<uint32_t*>(&t);
}

// baseline-PTX tensor ops (HMMA/LDSM SASS on sm_103)
#define LDSM4(R, addr) \
    asm volatile("ldmatrix.sync.aligned.m8n8.x4.shared.b16 {%0,%1,%2,%3}, [%4];" \
        : "=r"((R)[0]), "=r"((R)[1]), "=r"((R)[2]), "=r"((R)[3]) : "r"(addr))
#define LDSM2(R, addr) \
    asm volatile("ldmatrix.sync.aligned.m8n8.x2.shared.b16 {%0,%1}, [%2];" \
        : "=r"((R)[0]), "=r"((R)[1]) : "r"(addr))
#define MMA_BF16(D, Ar, Br) \
    asm volatile("mma.sync.aligned.m16n8k16.row.col.f32.bf16.bf16.f32 " \
        "{%0,%1,%2,%3}, {%4,%5,%6,%7}, {%8,%9}, {%0,%1,%2,%3};" \
        : "+f"((D)[0]), "+f"((D)[1]), "+f"((D)[2]), "+f"((D)[3]) \
        : "r"((Ar)[0]), "r"((Ar)[1]), "r"((Ar)[2]), "r"((Ar)[3]), \
          "r"((Br)[0]), "r"((Br)[1]))

// ---------------- CSR build -------------------------------------------------------
__global__ void hist(const int* __restrict__ ei, int E, int stride) {
    int t = blockIdx.x * blockDim.x + threadIdx.x;
#pragma unroll
    for (int k = 0; k < 4; k++) {
        int e = t + k * stride;
        if (e < E) atomicAdd(&g_cnt[ei[E + e]], 1);
    }
}
__global__ void scan_rowptr(int N) {
    __shared__ int s_sum[1024];
    int t = threadIdx.x;
    int chunk = (N + 1023) >> 10;
    int b0 = t * chunk, b1 = min(b0 + chunk, N);
    int s = 0;
    for (int i = b0; i < b1; i++) s += g_cnt[i] + 1;   // +1 self-loop
    s_sum[t] = s;
    __syncthreads();
    for (int off = 1; off < 1024; off <<= 1) {
        int v = (t >= off) ? s_sum[t - off] : 0;
        __syncthreads();
        s_sum[t] += v;
        __syncthreads();
    }
    int run = (t == 0) ? 0 : s_sum[t - 1];
    for (int i = b0; i < b1; i++) {
        int c = g_cnt[i] + 1;
        g_rowptr[i] = run;
        g_cnt[i] = run;          // cursor for fill
        run += c;
    }
    if (t == 1023) g_rowptr[N] = s_sum[1023];
}
// fill + tail blocks zero as2/ad2/stats (eCsr orders these before their consumers)
__global__ void fill_csr(const int* __restrict__ ei, int E, int N,
                         int stride, int fillBlks) {
    if ((int)blockIdx.x >= fillBlks) {
        int t = (blockIdx.x - fillBlks) * 256 + threadIdx.x;
        int zstride = (gridDim.x - fillBlks) * 256;
        for (int i = t; i < N; i += zstride) { g_as2[i] = 0.f; g_ad2[i] = 0.f; }
        if (t < 512) g_stats[t] = 0.f;
        return;
    }
    int t = blockIdx.x * blockDim.x + threadIdx.x;
    int tot = E + N;
#pragma unroll
    for (int k = 0; k < 4; k++) {
        int e = t + k * stride;
        if (e < tot) {
            int s, d;
            if (e < E) { s = ei[e]; d = ei[E + e]; }
            else       { s = d = e - E; }
            int pos = atomicAdd(&g_cnt[d], 1);
            g_csrc[pos] = s;
        }
    }
}

// ---------------- warp-mma bf16-split GEMM (512 threads, warp tile 16x64) --------
// C[128,128] tile = X[128,128] @ W[128,128]; D = XhiWhi + XhiWlo + XloWhi, fp32 acc.
// 512 threads (16 warps); warp w: rows (w&7)*16, cols (w>>3)*64 (1 m-tile x 8
// n-tiles = 32 accumulators/thread -> no register spills, 16 warps/SM).
// SMEM (bf16, row stride 136): Xhi | Xlo | WThi | WTlo  (WT = W transposed [n][k]).
// MODE 0: C += bias (p0). MODE 1: 4-head logits -> g_as1/g_ad1 (p0/p1 = att).
// MODE 2: X := relu(BN1(A)); 1-head logits -> atomicAdd g_as2/g_ad2.
#define TGS 136                 // padded bf16 row stride
#define OFF_XHI 0
#define OFF_XLO 34816
#define OFF_WHI 69632
#define OFF_WLO 104448
#define TG_SMEM 139264

template<int MODE>
__global__ void __launch_bounds__(512, 1)
tgemm(const float* __restrict__ A, const float* __restrict__ W,
      const float* __restrict__ p0, const float* __restrict__ p1,
      const float* __restrict__ gamma, const float* __restrict__ beta,
      float* __restrict__ C, int nrows) {
    extern __shared__ char smem[];
    __shared__ float sb0[128], sb1[128];
    __shared__ float s_sc[128], s_off[128];
    uint32_t sb = smem_to_u32(smem);
    const int tid = threadIdx.x;
    const int lane = tid & 31, w = tid >> 5;
    const int rb0 = blockIdx.x * 128;

    if (tid < 128) {
        sb0[tid] = p0[tid];
        if (MODE >= 1) sb1[tid] = p1[tid];
        if (MODE == 2) {
            float invN = 1.f / (float)nrows;
            float mu = g_stats[tid] * invN;
            float var = g_stats[128 + tid] * invN - mu * mu;
            float sc = gamma[tid] * rsqrtf(var + BN_EPS);
            s_sc[tid] = sc;
            s_off[tid] = beta[tid] - mu * sc;
        }
    }
    __syncthreads();   // s_sc needed by X staging in MODE 2

    // ---- W[k][n] -> WT[n][k] hi/lo bf16 (coalesced reads) ----
    for (int idx = tid; idx < 16384; idx += 512) {
        int k = idx >> 7, n = idx & 127;
        float wv = W[k * 128 + n];
        __nv_bfloat16 hb = __float2bfloat16_rn(wv);
        float hf = __bfloat162float(hb);
        __nv_bfloat16 lb = __float2bfloat16_rn(wv - hf);
        int off = (n * TGS + k) * 2;
        *(__nv_bfloat16*)(smem + OFF_WHI + off) = hb;
        *(__nv_bfloat16*)(smem + OFF_WLO + off) = lb;
    }

    // ---- X rows -> Xhi/Xlo bf16 (BN1+relu fused in MODE 2) ----
    {
        const float4* A4 = (const float4*)A;
        for (int i = tid; i < 4096; i += 512) {
            int r = i >> 5, kk = i & 31;   // kk = float4 index (4 channels)
            int row = rb0 + r;
            float4 v = make_float4(0.f, 0.f, 0.f, 0.f);
            if (row < nrows) {
                v = A4[(long)row * 32 + kk];
                if (MODE == 2) {
                    int c0 = kk * 4;
                    v.x = fmaxf(fmaf(v.x, s_sc[c0 + 0], s_off[c0 + 0]), 0.f);
                    v.y = fmaxf(fmaf(v.y, s_sc[c0 + 1], s_off[c0 + 1]), 0.f);
                    v.z = fmaxf(fmaf(v.z, s_sc[c0 + 2], s_off[c0 + 2]), 0.f);
                    v.w = fmaxf(fmaf(v.w, s_sc[c0 + 3], s_off[c0 + 3]), 0.f);
                }
            }
            float hx = __bfloat162float(__float2bfloat16_rn(v.x));
            float hy = __bfloat162float(__float2bfloat16_rn(v.y));
            float hz = __bfloat162float(__float2bfloat16_rn(v.z));
            float hw = __bfloat162float(__float2bfloat16_rn(v.w));
            uint2 hh = make_uint2(f2bf2(hx, hy), f2bf2(hz, hw));
            uint2 ll = make_uint2(f2bf2(v.x - hx, v.y - hy), f2bf2(v.z - hz, v.w - hw));
            int off = (r * TGS + kk * 4) * 2;
            *(uint2*)(smem + OFF_XHI + off) = hh;
            *(uint2*)(smem + OFF_XLO + off) = ll;
        }
    }
    __syncthreads();

    // ---- mainloop: 3 split terms, K in 8 steps of 16 ----
    const int rowg = (w & 7) * 16;       // 8 row groups of 16
    const int colg = (w >> 3) * 64;      // 2 col groups of 64
    float d[8][4];
#pragma unroll
    for (int nt = 0; nt < 8; nt++)
#pragma unroll
        for (int q = 0; q < 4; q++) d[nt][q] = 0.f;

    const int aRow = (lane & 7) + ((lane >> 3) & 1) * 8;  // row within m16 tile
    const int aKof = (lane >> 4) * 8;                     // k offset within k16
    const int bRow = lane & 7;                            // n within n8 tile
    const int bKof = ((lane >> 3) & 1) * 8;

    const uint32_t xbs[3] = { sb + OFF_XHI, sb + OFF_XHI, sb + OFF_XLO };
    const uint32_t wbs[3] = { sb + OFF_WHI, sb + OFF_WLO, sb + OFF_WHI };
#pragma unroll
    for (int t = 0; t < 3; t++) {
        uint32_t Xb = xbs[t], Wb = wbs[t];
#pragma unroll
        for (int kt = 0; kt < 8; kt++) {
            uint32_t a0[4];
            uint32_t aAddr = Xb + (uint32_t)(((rowg + aRow) * TGS + kt * 16 + aKof) * 2);
            LDSM4(a0, aAddr);
            uint32_t b[8][2];
#pragma unroll
            for (int nt = 0; nt < 8; nt++) {
                uint32_t bAddr = Wb + (uint32_t)(((colg + nt * 8 + bRow) * TGS + kt * 16 + bKof) * 2);
                LDSM2(b[nt], bAddr);
            }
#pragma unroll
            for (int nt = 0; nt < 8; nt++) {
                MMA_BF16(d[nt], a0, b[nt]);
            }
        }
    }

    // ---- epilogue ----
    const int qr = lane >> 2;
    const int qc = (lane & 3) * 2;
    const int hA = (colg >> 5), hB = hA + 1;   // heads covered by this warp (MODE 1)

    {
        int r0 = rb0 + rowg + qr;
        int r1 = r0 + 8;
        if (MODE == 0) {
#pragma unroll
            for (int nt = 0; nt < 8; nt++) {
                int c = colg + nt * 8 + qc;
                float b0 = sb0[c], b1 = sb0[c + 1];
                if (r0 < nrows)
                    *(float2*)&C[(long)r0 * 128 + c] =
                        make_float2(d[nt][0] + b0, d[nt][1] + b1);
                if (r1 < nrows)
                    *(float2*)&C[(long)r1 * 128 + c] =
                        make_float2(d[nt][2] + b0, d[nt][3] + b1);
            }
        } else {
            float psA0 = 0.f, pdA0 = 0.f, psB0 = 0.f, pdB0 = 0.f;
            float psA1 = 0.f, pdA1 = 0.f, psB1 = 0.f, pdB1 = 0.f;
#pragma unroll
            for (int nt = 0; nt < 8; nt++) {
                int c = colg + nt * 8 + qc;
                float a0 = sb0[c], a1 = sb0[c + 1];
                float e0 = sb1[c], e1 = sb1[c + 1];
                float q0s = d[nt][0] * a0 + d[nt][1] * a1;
                float q0d = d[nt][0] * e0 + d[nt][1] * e1;
                float q1s = d[nt][2] * a0 + d[nt][3] * a1;
                float q1d = d[nt][2] * e0 + d[nt][3] * e1;
                if (nt < 4) { psA0 += q0s; pdA0 += q0d; psA1 += q1s; pdA1 += q1d; }
                else        { psB0 += q0s; pdB0 += q0d; psB1 += q1s; pdB1 += q1d; }
                if (r0 < nrows)
                    *(float2*)&C[(long)r0 * 128 + c] = make_float2(d[nt][0], d[nt][1]);
                if (r1 < nrows)
                    *(float2*)&C[(long)r1 * 128 + c] = make_float2(d[nt][2], d[nt][3]);
            }
            // reduce over the 4 lanes sharing a row (segments of width 4)
#define QRED(v) { v += __shfl_down_sync(0xffffffffu, v, 2, 4); \
                  v += __shfl_down_sync(0xffffffffu, v, 1, 4); }
            QRED(psA0) QRED(pdA0) QRED(psB0) QRED(pdB0)
            QRED(psA1) QRED(pdA1) QRED(psB1) QRED(pdB1)
#undef QRED
            if ((lane & 3) == 0) {
                if (MODE == 1) {
                    if (r0 < nrows) {
                        g_as1[r0 * 4 + hA] = psA0; g_ad1[r0 * 4 + hA] = pdA0;
                        g_as1[r0 * 4 + hB] = psB0; g_ad1[r0 * 4 + hB] = pdB0;
                    }
                    if (r1 < nrows) {
                        g_as1[r1 * 4 + hA] = psA1; g_ad1[r1 * 4 + hA] = pdA1;
                        g_as1[r1 * 4 + hB] = psB1; g_ad1[r1 * 4 + hB] = pdB1;
                    }
                } else {
                    if (r0 < nrows) {
                        atomicAdd(&g_as2[r0], psA0 + psB0);
                        atomicAdd(&g_ad2[r0], pdA0 + pdB0);
                    }
                    if (r1 < nrows) {
                        atomicAdd(&g_as2[r1], psA1 + psB1);
                        atomicAdd(&g_ad2[r1], pdA1 + pdB1);
                    }
                }
            }
        }
    }
}

// ---- final GEMM [N,128]x[128,32], fused BN2+relu+residual+1/sqrt2 --------------
__global__ void gemm32f(const float* __restrict__ A, const float* __restrict__ W,
                        const float* __restrict__ bias_fin,
                        const float* __restrict__ gamma2,
                        const float* __restrict__ beta2,
                        const float* __restrict__ Rres,
                        float* __restrict__ C, int nrows) {
    __shared__ float Ws[128 * 32];
    __shared__ float Xs[32 * 128];
    __shared__ float s_sc[128], s_off[128];
    int tid = threadIdx.x;
    {
        float invN = 1.f / (float)nrows;
        float mu = g_stats[256 + tid] * invN;
        float var = g_stats[384 + tid] * invN - mu * mu;
        float sc = gamma2[tid] * rsqrtf(var + BN_EPS);
        s_sc[tid] = sc;
        s_off[tid] = beta2[tid] - mu * sc;
    }
    for (int i = tid; i < 4096; i += 128) Ws[i] = W[i];
    int w = tid >> 5, l = tid & 31;
    float bv = bias_fin[l];
    int rb0 = blockIdx.x * 128;
    const float4* A4 = (const float4*)A;
    const float4* R4 = (const float4*)Rres;

    for (int t = 0; t < 4; t++) {
        int rbase = rb0 + t * 32;
        __syncthreads();
        float4* Xs4 = (float4*)Xs;
        for (int i = tid; i < 1024; i += 128) {
            int r = i >> 5, cc = i & 31;
            int rrow = rbase + r;
            float4 xv = make_float4(0.f, 0.f, 0.f, 0.f);
            if (rrow < nrows) {
                float4 raw = A4[(long)rrow * 32 + cc];
                float4 rs  = R4[(long)rrow * 32 + cc];
                int c0 = cc * 4;
                float v;
                v = fmaxf(fmaf(raw.x, s_sc[c0 + 0], s_off[c0 + 0]), 0.f);
                xv.x = (v + rs.x) * INV_SQRT2;
                v = fmaxf(fmaf(raw.y, s_sc[c0 + 1], s_off[c0 + 1]), 0.f);
                xv.y = (v + rs.y) * INV_SQRT2;
                v = fmaxf(fmaf(raw.z, s_sc[c0 + 2], s_off[c0 + 2]), 0.f);
                xv.z = (v + rs.z) * INV_SQRT2;
                v = fmaxf(fmaf(raw.w, s_sc[c0 + 3], s_off[c0 + 3]), 0.f);
                xv.w = (v + rs.w) * INV_SQRT2;
            }
            Xs4[i] = xv;
        }
        __syncthreads();
        float acc[8] = {};
#pragma unroll 4
        for (int k = 0; k < 128; k++) {
            float wv = Ws[k * 32 + l];
#pragma unroll
            for (int r = 0; r < 8; r++)
                acc[r] = fmaf(Xs[(w * 8 + r) * 128 + k], wv, acc[r]);
        }
#pragma unroll
        for (int r = 0; r < 8; r++) {
            int rrow = rbase + w * 8 + r;
            if (rrow < nrows) C[(long)rrow * 32 + l] = acc[r] + bv;
        }
    }
}

// ---------------- aggregation + fused BN stats ------------------------------------
// agg1 tail blocks re-zero g_cnt for the next call (after fill_csr's last use).
__global__ void agg1(const float* __restrict__ bias, int N, int aggBlks) {
    if ((int)blockIdx.x >= aggBlks) {
        int t = (blockIdx.x - aggBlks) * 256 + threadIdx.x;
        int stride = (gridDim.x - aggBlks) * 256;
        for (int i = t; i < N; i += stride) g_cnt[i] = 0;
        return;
    }
    __shared__ int   s_src[8][32];
    __shared__ float s_ee [8][128];
    __shared__ float s_stat[256];
    int tid = threadIdx.x;
    s_stat[tid] = 0.f;
    __syncthreads();
    int wl = tid >> 5;
    int gw = (blockIdx.x * blockDim.x + tid) >> 5;
    int l = tid & 31;
    if (gw < N) {
        int beg = __ldg(&g_rowptr[gw]), end = __ldg(&g_rowptr[gw + 1]);
        float4 adv = *(const float4*)(g_ad1 + gw * 4);
        int head = l >> 3;
        float4 acc = make_float4(0.f, 0.f, 0.f, 0.f);
        float4 den = make_float4(0.f, 0.f, 0.f, 0.f);
        for (int base = beg; base < end; base += 32) {
            int e = base + l;
            if (e < end) {
                int s = __ldg(&g_csrc[e]);
                float4 as = *(const float4*)(g_as1 + s * 4);
                float vx = as.x + adv.x; vx = vx > 0.f ? vx : NEG_SLOPE * vx;
                float vy = as.y + adv.y; vy = vy > 0.f ? vy : NEG_SLOPE * vy;
                float vz = as.z + adv.z; vz = vz > 0.f ? vz : NEG_SLOPE * vz;
                float vw = as.w + adv.w; vw = vw > 0.f ? vw : NEG_SLOPE * vw;
                float4 ee;
                ee.x = __expf(vx); ee.y = __expf(vy);
                ee.z = __expf(vz); ee.w = __expf(vw);
                den.x += ee.x; den.y += ee.y; den.z += ee.z; den.w += ee.w;
                s_src[wl][l] = s;
                ((float4*)s_ee[wl])[l] = ee;
            }
            __syncwarp();
            int cnt = min(32, end - base);
            int j = 0;
            for (; j + 4 <= cnt; j += 4) {
                int s0 = s_src[wl][j],     s1 = s_src[wl][j + 1];
                int s2 = s_src[wl][j + 2], s3 = s_src[wl][j + 3];
                float e0 = s_ee[wl][(j    ) * 4 + head];
                float e1 = s_ee[wl][(j + 1) * 4 + head];
                float e2 = s_ee[wl][(j + 2) * 4 + head];
                float e3 = s_ee[wl][(j + 3) * 4 + head];
                float4 h0 = *(const float4*)(g_h1 + (long)s0 * 128 + l * 4);
                float4 h1 = *(const float4*)(g_h1 + (long)s1 * 128 + l * 4);
                float4 h2 = *(const float4*)(g_h1 + (long)s2 * 128 + l * 4);
                float4 h3 = *(const float4*)(g_h1 + (long)s3 * 128 + l * 4);
                FMA4(acc, e0, h0);
                FMA4(acc, e1, h1);
                FMA4(acc, e2, h2);
                FMA4(acc, e3, h3);
            }
            for (; j < cnt; j++) {
                int ss   = s_src[wl][j];
                float eh = s_ee[wl][j * 4 + head];
                float4 hv = *(const float4*)(g_h1 + (long)ss * 128 + l * 4);
                FMA4(acc, eh, hv);
            }
            __syncwarp();
        }
#pragma unroll
        for (int off = 16; off; off >>= 1) {
            den.x += __shfl_xor_sync(0xffffffffu, den.x, off);
            den.y += __shfl_xor_sync(0xffffffffu, den.y, off);
            den.z += __shfl_xor_sync(0xffffffffu, den.z, off);
            den.w += __shfl_xor_sync(0xffffffffu, den.w, off);
        }
        float dh = head == 0 ? den.x : head == 1 ? den.y : head == 2 ? den.z : den.w;
        float inv = __fdividef(1.f, dh + 1e-16f);
        float4 bv = ((const float4*)bias)[l];
        float4 o = make_float4(acc.x * inv + bv.x, acc.y * inv + bv.y,
                               acc.z * inv + bv.z, acc.w * inv + bv.w);
        ((float4*)g_out1)[(long)gw * 32 + l] = o;
        int c0 = l * 4;
        atomicAdd(&s_stat[c0 + 0], o.x);
        atomicAdd(&s_stat[c0 + 1], o.y);
        atomicAdd(&s_stat[c0 + 2], o.z);
        atomicAdd(&s_stat[c0 + 3], o.w);
        atomicAdd(&s_stat[128 + c0 + 0], o.x * o.x);
        atomicAdd(&s_stat[128 + c0 + 1], o.y * o.y);
        atomicAdd(&s_stat[128 + c0 + 2], o.z * o.z);
        atomicAdd(&s_stat[128 + c0 + 3], o.w * o.w);
    }
    __syncthreads();
    atomicAdd(&g_stats[tid], s_stat[tid]);
}

__global__ void agg2(const float* __restrict__ bias, int N) {
    __shared__ int   s_src[8][32];
    __shared__ float s_ee [8][32];
    __shared__ float s_stat[256];
    int tid = threadIdx.x;
    s_stat[tid] = 0.f;
    __syncthreads();
    int wl = tid >> 5;
    int gw = (blockIdx.x * blockDim.x + tid) >> 5;
    int l = tid & 31;
    if (gw < N) {
        int beg = __ldg(&g_rowptr[gw]), end = __ldg(&g_rowptr[gw + 1]);
        float adv = g_ad2[gw];
        float4 acc = make_float4(0.f, 0.f, 0.f, 0.f);
        float den = 0.f;
        for (int base = beg; base < end; base += 32) {
            int e = base + l;
            if (e < end) {
                int s = __ldg(&g_csrc[e]);
                float v = __ldg(g_as2 + s) + adv;
                v = v > 0.f ? v : NEG_SLOPE * v;
                float ee = __expf(v);
                den += ee;
                s_src[wl][l] = s;
                s_ee[wl][l] = ee;
            }
            __syncwarp();
            int cnt = min(32, end - base);
            int j = 0;
            for (; j + 4 <= cnt; j += 4) {
                int s0 = s_src[wl][j],     s1 = s_src[wl][j + 1];
                int s2 = s_src[wl][j + 2], s3 = s_src[wl][j + 3];
                float e0 = s_ee[wl][j],     e1 = s_ee[wl][j + 1];
                float e2 = s_ee[wl][j + 2], e3 = s_ee[wl][j + 3];
                float4 h0 = *(const float4*)(g_h2 + (long)s0 * 128 + l * 4);
                float4 h1 = *(const float4*)(g_h2 + (long)s1 * 128 + l * 4);
                float4 h2 = *(const float4*)(g_h2 + (long)s2 * 128 + l * 4);
                float4 h3 = *(const float4*)(g_h2 + (long)s3 * 128 + l * 4);
                FMA4(acc, e0, h0);
                FMA4(acc, e1, h1);
                FMA4(acc, e2, h2);
                FMA4(acc, e3, h3);
            }
            for (; j < cnt; j++) {
                int ss   = s_src[wl][j];
                float ej = s_ee[wl][j];
                float4 hv = *(const float4*)(g_h2 + (long)ss * 128 + l * 4);
                FMA4(acc, ej, hv);
            }
            __syncwarp();
        }
#pragma unroll
        for (int off = 16; off; off >>= 1)
            den += __shfl_xor_sync(0xffffffffu, den, off);
        float inv = __fdividef(1.f, den + 1e-16f);
        float4 bv = ((const float4*)bias)[l];
        float4 o = make_float4(acc.x * inv + bv.x, acc.y * inv + bv.y,
                               acc.z * inv + bv.z, acc.w * inv + bv.w);
        ((float4*)g_out2)[(long)gw * 32 + l] = o;
        int c0 = l * 4;
        atomicAdd(&s_stat[c0 + 0], o.x);
        atomicAdd(&s_stat[c0 + 1], o.y);
        atomicAdd(&s_stat[c0 + 2], o.z);
        atomicAdd(&s_stat[c0 + 3], o.w);
        atomicAdd(&s_stat[128 + c0 + 0], o.x * o.x);
        atomicAdd(&s_stat[128 + c0 + 1], o.y * o.y);
        atomicAdd(&s_stat[128 + c0 + 2], o.z * o.z);
        atomicAdd(&s_stat[128 + c0 + 3], o.w * o.w);
    }
    __syncthreads();
    atomicAdd(&g_stats[256 + tid], s_stat[tid]);
}

// ---------------- launch ------------------------------------------------------
extern "C" void kernel_launch(void* const* d_in, const int* in_sizes, int n_in,
                              void* d_out, int out_size) {
    const float* x        = (const float*)d_in[0];
    const int*   ei       = (const int*)  d_in[1];
    const float* W1       = (const float*)d_in[2];
    const float* att_src1 = (const float*)d_in[3];
    const float* att_dst1 = (const float*)d_in[4];
    const float* bias1    = (const float*)d_in[5];
    const float* W2       = (const float*)d_in[6];
    const float* att_src2 = (const float*)d_in[7];
    const float* att_dst2 = (const float*)d_in[8];
    const float* bias2    = (const float*)d_in[9];
    const float* gamma1   = (const float*)d_in[10];
    const float* beta1    = (const float*)d_in[11];
    const float* gamma2   = (const float*)d_in[12];
    const float* beta2    = (const float*)d_in[13];
    const float* W_res    = (const float*)d_in[14];
    const float* b_res    = (const float*)d_in[15];
    const float* W_fin    = (const float*)d_in[16];
    const float* b_fin    = (const float*)d_in[17];
    float* out = (float*)d_out;

    int N = in_sizes[0] / 128;
    int E = in_sizes[1] / 2;
    int tot = E + N;

    float *p_h1, *p_out1, *p_h2, *p_out2, *p_res;
    cudaGetSymbolAddress((void**)&p_h1,   g_h1);
    cudaGetSymbolAddress((void**)&p_out1, g_out1);
    cudaGetSymbolAddress((void**)&p_h2,   g_h2);
    cudaGetSymbolAddress((void**)&p_out2, g_out2);
    cudaGetSymbolAddress((void**)&p_res,  g_res);

    cudaFuncSetAttribute(tgemm<0>, cudaFuncAttributeMaxDynamicSharedMemorySize, TG_SMEM);
    cudaFuncSetAttribute(tgemm<1>, cudaFuncAttributeMaxDynamicSharedMemorySize, TG_SMEM);
    cudaFuncSetAttribute(tgemm<2>, cudaFuncAttributeMaxDynamicSharedMemorySize, TG_SMEM);

    static cudaStream_t sA = 0, sB = 0;
    static cudaEvent_t  eFork = 0, eA4 = 0, eCsr = 0, eRes = 0;
    static int s_init = 0;
    if (!s_init) {
        s_init = 1;
        cudaStreamCreateWithFlags(&sA, cudaStreamNonBlocking);
        cudaStreamCreateWithFlags(&sB, cudaStreamNonBlocking);
        cudaEventCreateWithFlags(&eFork, cudaEventDisableTiming);
        cudaEventCreateWithFlags(&eA4,   cudaEventDisableTiming);
        cudaEventCreateWithFlags(&eCsr,  cudaEventDisableTiming);
        cudaEventCreateWithFlags(&eRes,  cudaEventDisableTiming);
    }

    int nrb = (N + 127) / 128;
    int aw = (N * 32 + 255) / 256;
    int cleanBlks = 64;

    cudaStream_t m = 0;

    // fork: CSR build chain on sA (g_cnt is zero from previous call / load-time)
    cudaEventRecord(eFork, m);
    cudaStreamWaitEvent(sA, eFork, 0);
    int hthreads = (E + 3) / 4;
    int hblocks = (hthreads + 255) / 256;
    hist<<<hblocks, 256, 0, sA>>>(ei, E, hblocks * 256);
    scan_rowptr<<<1, 1024, 0, sA>>>(N);
    int fthreads = (tot + 3) / 4;
    int fblocks = (fthreads + 255) / 256;
    fill_csr<<<fblocks + 64, 256, 0, sA>>>(ei, E, N, fblocks * 256, fblocks);
    cudaEventRecord(eCsr, sA);

    // main: conv1 tensor GEMM (+4-head logits)
    tgemm<1><<<nrb, 512, TG_SMEM, m>>>(x, W1, att_src1, att_dst1,
                                       nullptr, nullptr, p_h1, N);

    // fork: residual tensor GEMM on sB (overlaps agg1)
    cudaEventRecord(eA4, m);
    cudaStreamWaitEvent(sB, eA4, 0);
    tgemm<0><<<nrb, 512, TG_SMEM, sB>>>(x, W_res, b_res, b_res,
                                        nullptr, nullptr, p_res, N);
    cudaEventRecord(eRes, sB);

    // main: join CSR, conv1 aggregation (+BN1 stats; tail re-zeroes g_cnt)
    cudaStreamWaitEvent(m, eCsr, 0);
    agg1<<<aw + cleanBlks, 256, 0, m>>>(bias1, N, aw);

    // conv2 tensor GEMM (BN1+relu fused, 1-head logits via atomics)
    tgemm<2><<<nrb, 512, TG_SMEM, m>>>(p_out1, W2, att_src2, att_dst2,
                                       gamma1, beta1, p_h2, N);
    agg2<<<aw, 256, 0, m>>>(bias2, N);

    // join residual, final projection
    cudaStreamWaitEvent(m, eRes, 0);
    gemm32f<<<(N + 127) / 128, 128, 0, m>>>(p_out2, W_fin, b_fin,
                                            gamma2, beta2, p_res, out, N);
}